// round 3
// baseline (speedup 1.0000x reference)
#include <cuda_runtime.h>
#include <cstdint>

#define NMAX 50000
#define EMAX 800000
#define FIN  128
#define FH   128
#define FOUT 64

// ---------------- scratch (device globals; allocation-free) ----------------
__device__ int   g_cnt[NMAX];          // in-degree counts (no self-loop)
__device__ int   g_bsum[256];          // per-block inclusive prefix totals
__device__ int   g_flag[256];          // chained-scan ready flags
__device__ int   g_off[NMAX + 1];      // CSR row offsets (by dst)
__device__ int   g_cur[NMAX];          // fill cursors
__device__ int   g_srcs[EMAX];         // CSR: source node per slot
__device__ float g_w[EMAX];            // CSR: edge weight isd[s]*isd[d]
__device__ float g_isd[NMAX];          // deg^-1/2
__device__ float g_idg[NMAX];          // deg^-1
__device__ float g_h1[(size_t)NMAX * FH];
__device__ float g_agg1[(size_t)NMAX * FH];
__device__ float g_h2[(size_t)NMAX * FOUT];

// ---------------------------------------------------------------------------
// CSR build
// ---------------------------------------------------------------------------
__global__ void k_count(const int* __restrict__ dst, int e) {
    int i = blockIdx.x * blockDim.x + threadIdx.x;
    if (i < e) atomicAdd(&g_cnt[dst[i]], 1);
}

// Single-kernel chained scan + degree finalize.
// Block b scans its 256 counts, waits for block b-1's published prefix,
// then writes offsets/cursors/deg terms. All blocks co-resident (196 x 256).
__global__ void k_scan_chain(int n, int e) {
    __shared__ int sh[256];
    __shared__ int s_prev;
    const int b = blockIdx.x;
    const int tid = threadIdx.x;
    const int i = b * 256 + tid;

    int c = (i < n) ? g_cnt[i] : 0;
    sh[tid] = c;
    __syncthreads();
#pragma unroll
    for (int d = 1; d < 256; d <<= 1) {
        int t = (tid >= d) ? sh[tid - d] : 0;
        __syncthreads();
        sh[tid] += t;
        __syncthreads();
    }
    int incl = sh[tid];

    if (tid == 0) {
        int prev = 0;
        if (b > 0) {
            while (atomicAdd(&g_flag[b - 1], 0) == 0) {}
            __threadfence();
            prev = g_bsum[b - 1];
        }
        s_prev = prev;
        g_bsum[b] = prev + sh[255];
        __threadfence();
        atomicExch(&g_flag[b], 1);
    }
    __syncthreads();
    const int prev = s_prev;

    if (i < n) {
        int excl = prev + incl - c;
        g_off[i] = excl;
        g_cur[i] = excl;
        float deg = (float)c + 1.0f;
        g_isd[i] = rsqrtf(deg);
        g_idg[i] = 1.0f / deg;
    }
    if (i == n) g_off[n] = e;
}

__global__ void k_fill(const int* __restrict__ src, const int* __restrict__ dst, int e) {
    int i = blockIdx.x * blockDim.x + threadIdx.x;
    if (i < e) {
        int s = src[i];
        int d = dst[i];
        int pos = atomicAdd(&g_cur[d], 1);
        g_srcs[pos] = s;
        g_w[pos] = g_isd[s] * g_isd[d];
    }
}

// ---------------------------------------------------------------------------
// GEMM-1: H = A @ W, A:[N,128], W:[128,128]. BM=BN=128, BK=16, 256 thr, 8x8.
// ---------------------------------------------------------------------------
__global__ void __launch_bounds__(256)
k_gemm128(const float* __restrict__ A, const float* __restrict__ W,
          float* __restrict__ Hout, int N) {
    constexpr int K = 128, BM = 128, BN = 128, BK = 16;
    __shared__ float As[BK][BM + 4];
    __shared__ float Ws[BK][BN];

    const int tid = threadIdx.x;
    const int rowBase = blockIdx.x * BM;
    const int ty = tid >> 4;         // 0..15 -> 8-row slab
    const int tx = tid & 15;         // 0..15 -> 8-col slab

    float acc[8][8];
#pragma unroll
    for (int i = 0; i < 8; i++)
#pragma unroll
        for (int j = 0; j < 8; j++) acc[i][j] = 0.0f;

    for (int k0 = 0; k0 < K; k0 += BK) {
#pragma unroll
        for (int l = 0; l < 2; l++) {
            int idx = tid + l * 256;
            int row = idx >> 2;              // 0..127
            int kq = (idx & 3) * 4;          // 0,4,8,12
            int r = rowBase + row;
            float4 av = make_float4(0.f, 0.f, 0.f, 0.f);
            if (r < N)
                av = *reinterpret_cast<const float4*>(A + (size_t)r * K + k0 + kq);
            As[kq + 0][row] = av.x;
            As[kq + 1][row] = av.y;
            As[kq + 2][row] = av.z;
            As[kq + 3][row] = av.w;
        }
#pragma unroll
        for (int l = 0; l < 2; l++) {
            int idx = tid + l * 256;
            int wk = idx >> 5;               // 0..15
            int wn = (idx & 31) * 4;         // 0..124
            *reinterpret_cast<float4*>(&Ws[wk][wn]) =
                *reinterpret_cast<const float4*>(W + (size_t)(k0 + wk) * BN + wn);
        }
        __syncthreads();

#pragma unroll
        for (int k = 0; k < BK; k++) {
            float4 a0 = *reinterpret_cast<const float4*>(&As[k][ty * 8]);
            float4 a1 = *reinterpret_cast<const float4*>(&As[k][ty * 8 + 4]);
            float4 b0 = *reinterpret_cast<const float4*>(&Ws[k][tx * 8]);
            float4 b1 = *reinterpret_cast<const float4*>(&Ws[k][tx * 8 + 4]);
            float a[8] = {a0.x, a0.y, a0.z, a0.w, a1.x, a1.y, a1.z, a1.w};
            float bb[8] = {b0.x, b0.y, b0.z, b0.w, b1.x, b1.y, b1.z, b1.w};
#pragma unroll
            for (int i = 0; i < 8; i++)
#pragma unroll
                for (int j = 0; j < 8; j++) acc[i][j] = fmaf(a[i], bb[j], acc[i][j]);
        }
        __syncthreads();
    }

    const int col = tx * 8;
#pragma unroll
    for (int i = 0; i < 8; i++) {
        int row = rowBase + ty * 8 + i;
        if (row < N) {
            *reinterpret_cast<float4*>(Hout + (size_t)row * BN + col) =
                make_float4(acc[i][0], acc[i][1], acc[i][2], acc[i][3]);
            *reinterpret_cast<float4*>(Hout + (size_t)row * BN + col + 4) =
                make_float4(acc[i][4], acc[i][5], acc[i][6], acc[i][7]);
        }
    }
}

// ---------------------------------------------------------------------------
// GEMM-2: H = relu(A) @ W, A:[N,128], W:[128,64]. BM=128, BN=64, 8x4 tile.
// ---------------------------------------------------------------------------
__global__ void __launch_bounds__(256)
k_gemm64(const float* __restrict__ A, const float* __restrict__ W,
         float* __restrict__ Hout, int N) {
    constexpr int K = 128, BM = 128, BN = 64, BK = 16;
    __shared__ float As[BK][BM + 4];
    __shared__ float Ws[BK][BN];

    const int tid = threadIdx.x;
    const int rowBase = blockIdx.x * BM;
    const int ty = tid >> 4;
    const int tx = tid & 15;
    const int wk = tid >> 4;
    const int wn = (tid & 15) * 4;

    float acc[8][4];
#pragma unroll
    for (int i = 0; i < 8; i++)
#pragma unroll
        for (int j = 0; j < 4; j++) acc[i][j] = 0.0f;

    for (int k0 = 0; k0 < K; k0 += BK) {
#pragma unroll
        for (int l = 0; l < 2; l++) {
            int idx = tid + l * 256;
            int row = idx >> 2;
            int kq = (idx & 3) * 4;
            int r = rowBase + row;
            float4 av = make_float4(0.f, 0.f, 0.f, 0.f);
            if (r < N)
                av = *reinterpret_cast<const float4*>(A + (size_t)r * K + k0 + kq);
            av.x = fmaxf(av.x, 0.f); av.y = fmaxf(av.y, 0.f);
            av.z = fmaxf(av.z, 0.f); av.w = fmaxf(av.w, 0.f);
            As[kq + 0][row] = av.x;
            As[kq + 1][row] = av.y;
            As[kq + 2][row] = av.z;
            As[kq + 3][row] = av.w;
        }
        *reinterpret_cast<float4*>(&Ws[wk][wn]) =
            *reinterpret_cast<const float4*>(W + (size_t)(k0 + wk) * BN + wn);
        __syncthreads();

#pragma unroll
        for (int k = 0; k < BK; k++) {
            float4 a0 = *reinterpret_cast<const float4*>(&As[k][ty * 8]);
            float4 a1 = *reinterpret_cast<const float4*>(&As[k][ty * 8 + 4]);
            float4 bv = *reinterpret_cast<const float4*>(&Ws[k][tx * 4]);
            float a[8] = {a0.x, a0.y, a0.z, a0.w, a1.x, a1.y, a1.z, a1.w};
            float b[4] = {bv.x, bv.y, bv.z, bv.w};
#pragma unroll
            for (int i = 0; i < 8; i++)
#pragma unroll
                for (int j = 0; j < 4; j++) acc[i][j] = fmaf(a[i], b[j], acc[i][j]);
        }
        __syncthreads();
    }

    const int col = tx * 4;
#pragma unroll
    for (int i = 0; i < 8; i++) {
        int row = rowBase + ty * 8 + i;
        if (row < N)
            *reinterpret_cast<float4*>(Hout + (size_t)row * BN + col) =
                make_float4(acc[i][0], acc[i][1], acc[i][2], acc[i][3]);
    }
}

// ---------------------------------------------------------------------------
// CSR gather: one warp per destination node, 4-way edge unroll for MLP.
//   Out[d] = sum_{e: dst=d} H[src_e]*w_e + H[d]*idg[d] + bias
// ---------------------------------------------------------------------------
template <int F>
__global__ void __launch_bounds__(256)
k_gather(const float* __restrict__ H, const float* __restrict__ bias,
         float* __restrict__ Out, int N) {
    int gw = (blockIdx.x * blockDim.x + threadIdx.x) >> 5;
    int lane = threadIdx.x & 31;
    if (gw >= N) return;
    const int beg = g_off[gw];
    const int end = g_off[gw + 1];

    if (F == 128) {
        float idg = g_idg[gw];
        float4 hv = *reinterpret_cast<const float4*>(H + (size_t)gw * 128 + lane * 4);
        float4 bv = *reinterpret_cast<const float4*>(bias + lane * 4);
        float4 acc = make_float4(fmaf(hv.x, idg, bv.x), fmaf(hv.y, idg, bv.y),
                                 fmaf(hv.z, idg, bv.z), fmaf(hv.w, idg, bv.w));
        int j = beg;
        for (; j + 4 <= end; j += 4) {
            int s0 = g_srcs[j], s1 = g_srcs[j+1], s2 = g_srcs[j+2], s3 = g_srcs[j+3];
            float w0 = g_w[j], w1 = g_w[j+1], w2 = g_w[j+2], w3 = g_w[j+3];
            float4 v0 = *reinterpret_cast<const float4*>(H + (size_t)s0 * 128 + lane * 4);
            float4 v1 = *reinterpret_cast<const float4*>(H + (size_t)s1 * 128 + lane * 4);
            float4 v2 = *reinterpret_cast<const float4*>(H + (size_t)s2 * 128 + lane * 4);
            float4 v3 = *reinterpret_cast<const float4*>(H + (size_t)s3 * 128 + lane * 4);
            acc.x = fmaf(v0.x, w0, acc.x); acc.y = fmaf(v0.y, w0, acc.y);
            acc.z = fmaf(v0.z, w0, acc.z); acc.w = fmaf(v0.w, w0, acc.w);
            acc.x = fmaf(v1.x, w1, acc.x); acc.y = fmaf(v1.y, w1, acc.y);
            acc.z = fmaf(v1.z, w1, acc.z); acc.w = fmaf(v1.w, w1, acc.w);
            acc.x = fmaf(v2.x, w2, acc.x); acc.y = fmaf(v2.y, w2, acc.y);
            acc.z = fmaf(v2.z, w2, acc.z); acc.w = fmaf(v2.w, w2, acc.w);
            acc.x = fmaf(v3.x, w3, acc.x); acc.y = fmaf(v3.y, w3, acc.y);
            acc.z = fmaf(v3.z, w3, acc.z); acc.w = fmaf(v3.w, w3, acc.w);
        }
        for (; j < end; j++) {
            int s = g_srcs[j]; float w = g_w[j];
            float4 v = *reinterpret_cast<const float4*>(H + (size_t)s * 128 + lane * 4);
            acc.x = fmaf(v.x, w, acc.x); acc.y = fmaf(v.y, w, acc.y);
            acc.z = fmaf(v.z, w, acc.z); acc.w = fmaf(v.w, w, acc.w);
        }
        *reinterpret_cast<float4*>(Out + (size_t)gw * 128 + lane * 4) = acc;
    } else {
        float idg = g_idg[gw];
        float2 hv = *reinterpret_cast<const float2*>(H + (size_t)gw * 64 + lane * 2);
        float2 bv = *reinterpret_cast<const float2*>(bias + lane * 2);
        float2 acc = make_float2(fmaf(hv.x, idg, bv.x), fmaf(hv.y, idg, bv.y));
        int j = beg;
        for (; j + 4 <= end; j += 4) {
            int s0 = g_srcs[j], s1 = g_srcs[j+1], s2 = g_srcs[j+2], s3 = g_srcs[j+3];
            float w0 = g_w[j], w1 = g_w[j+1], w2 = g_w[j+2], w3 = g_w[j+3];
            float2 v0 = *reinterpret_cast<const float2*>(H + (size_t)s0 * 64 + lane * 2);
            float2 v1 = *reinterpret_cast<const float2*>(H + (size_t)s1 * 64 + lane * 2);
            float2 v2 = *reinterpret_cast<const float2*>(H + (size_t)s2 * 64 + lane * 2);
            float2 v3 = *reinterpret_cast<const float2*>(H + (size_t)s3 * 64 + lane * 2);
            acc.x = fmaf(v0.x, w0, acc.x); acc.y = fmaf(v0.y, w0, acc.y);
            acc.x = fmaf(v1.x, w1, acc.x); acc.y = fmaf(v1.y, w1, acc.y);
            acc.x = fmaf(v2.x, w2, acc.x); acc.y = fmaf(v2.y, w2, acc.y);
            acc.x = fmaf(v3.x, w3, acc.x); acc.y = fmaf(v3.y, w3, acc.y);
        }
        for (; j < end; j++) {
            int s = g_srcs[j]; float w = g_w[j];
            float2 v = *reinterpret_cast<const float2*>(H + (size_t)s * 64 + lane * 2);
            acc.x = fmaf(v.x, w, acc.x); acc.y = fmaf(v.y, w, acc.y);
        }
        *reinterpret_cast<float2*>(Out + (size_t)gw * 64 + lane * 2) = acc;
    }
}

// ---------------------------------------------------------------------------
// Launch: fork CSR build onto a side stream so it overlaps GEMM-1.
// Side stream + events created once on the first (correctness, non-capture)
// call; the captured graph records the cross-stream dependencies.
// ---------------------------------------------------------------------------
extern "C" void kernel_launch(void* const* d_in, const int* in_sizes, int n_in,
                              void* d_out, int out_size) {
    const float* x  = (const float*)d_in[0];
    const int* eidx = (const int*)d_in[1];
    const float* W1 = (const float*)d_in[2];
    const float* b1 = (const float*)d_in[3];
    const float* W2 = (const float*)d_in[4];
    const float* b2 = (const float*)d_in[5];
    float* out = (float*)d_out;

    const int N = in_sizes[0] / FIN;   // 50000
    const int E = in_sizes[1] / 2;     // 800000
    const int* src = eidx;
    const int* dst = eidx + E;

    static cudaStream_t s2 = nullptr;
    static cudaEvent_t evFork = nullptr, evBuild = nullptr;
    if (!s2) {
        cudaStreamCreateWithFlags(&s2, cudaStreamNonBlocking);
        cudaEventCreateWithFlags(&evFork, cudaEventDisableTiming);
        cudaEventCreateWithFlags(&evBuild, cudaEventDisableTiming);
    }

    float *h1, *agg1, *h2;
    void *cntp, *flagp;
    cudaGetSymbolAddress((void**)&h1, g_h1);
    cudaGetSymbolAddress((void**)&agg1, g_agg1);
    cudaGetSymbolAddress((void**)&h2, g_h2);
    cudaGetSymbolAddress(&cntp, g_cnt);
    cudaGetSymbolAddress(&flagp, g_flag);

    const int nScanBlocks = (N + 255) / 256;
    const int rowBlocks = (N + 127) / 128;
    const int gatherBlocks = (N * 32 + 255) / 256;

    // Fork: CSR build on s2, GEMM-1 on main stream.
    cudaEventRecord(evFork, 0);
    cudaStreamWaitEvent(s2, evFork, 0);

    cudaMemsetAsync(cntp, 0, (size_t)N * sizeof(int), s2);
    cudaMemsetAsync(flagp, 0, 256 * sizeof(int), s2);
    k_count<<<(E + 255) / 256, 256, 0, s2>>>(dst, E);
    k_scan_chain<<<nScanBlocks, 256, 0, s2>>>(N, E);
    k_fill<<<(E + 255) / 256, 256, 0, s2>>>(src, dst, E);
    cudaEventRecord(evBuild, s2);

    // GEMM-1 concurrently on main stream.
    k_gemm128<<<rowBlocks, 256>>>(x, W1, h1, N);

    // Join, then the serial tail.
    cudaStreamWaitEvent(0, evBuild, 0);
    k_gather<FH><<<gatherBlocks, 256>>>(h1, b1, agg1, N);
    k_gemm64<<<rowBlocks, 256>>>(agg1, W2, h2, N);
    k_gather<FOUT><<<gatherBlocks, 256>>>(h2, b2, out, N);
}